// round 6
// baseline (speedup 1.0000x reference)
#include <cuda_runtime.h>
#include <math.h>

// Problem dims (fixed by setup_inputs)
constexpr int B = 8, H = 384, W = 768;
constexpr int HW = H * W;              // 294912
constexpr int NPIX = B * HW;           // 2359296

// Accumulators: 0 photo_fw, 1 photo_bw, 2 census_fw, 3 census_bw, 4 mask_fw_sum, 5 mask_bw_sum
// Zero-initialized at module load; k_final re-zeroes after reading each call.
__device__ double g_acc[6];

// Scratch gray maps (intensity*255) and backward mask
__device__ float g_g1[NPIX];    // gray(img1)*255
__device__ float g_g2[NPIX];    // gray(img2)*255
__device__ float g_g1w[NPIX];   // gray(warp(img1, flow_bw))*255
__device__ float g_g2w[NPIX];   // gray(warp(img2, flow_fw))*255
__device__ float g_maskbw[NPIX];

struct Bilin {
    int i00, i01, i10, i11;
    float w00, w01, w10, w11;
};

__device__ __forceinline__ Bilin make_bilin(float fx, float fy, int x, int y) {
    float gx = fminf(fmaxf(fx + (float)x, 0.0f), (float)(W - 1));
    float gy = fminf(fmaxf(fy + (float)y, 0.0f), (float)(H - 1));
    float x0 = floorf(gx), y0 = floorf(gy);
    float wx = gx - x0, wy = gy - y0;
    int x0i = (int)x0, y0i = (int)y0;
    int x1i = min(x0i + 1, W - 1);
    int y1i = min(y0i + 1, H - 1);
    Bilin b;
    b.i00 = y0i * W + x0i;
    b.i01 = y0i * W + x1i;
    b.i10 = y1i * W + x0i;
    b.i11 = y1i * W + x1i;
    float ix = 1.0f - wx, iy = 1.0f - wy;
    b.w00 = ix * iy; b.w01 = wx * iy; b.w10 = ix * wy; b.w11 = wx * wy;
    return b;
}

__device__ __forceinline__ float samp(const float* __restrict__ p, const Bilin& bl) {
    return bl.w00 * __ldg(p + bl.i00) + bl.w01 * __ldg(p + bl.i01)
         + bl.w10 * __ldg(p + bl.i10) + bl.w11 * __ldg(p + bl.i11);
}

__device__ __forceinline__ float warp_reduce(float v) {
    #pragma unroll
    for (int o = 16; o > 0; o >>= 1) v += __shfl_down_sync(0xFFFFFFFFu, v, o);
    return v;
}

// Per-pixel: occ fw/bw, photometric loss partials, gray maps
__global__ void __launch_bounds__(256) k_main(const float* __restrict__ img1,
                                              const float* __restrict__ img2,
                                              const float* __restrict__ ffw,
                                              const float* __restrict__ fbw,
                                              float* __restrict__ out) {
    int i = blockIdx.x * blockDim.x + threadIdx.x;   // grid sized exactly
    int b = i / HW;
    int r = i - b * HW;
    int y = r / W;
    int x = r - y * W;

    const float* f1 = ffw + (size_t)b * 2 * HW;
    const float* f2 = fbw + (size_t)b * 2 * HW;
    float fwx = f1[r],       fwy = f1[HW + r];
    float bwx = f2[r],       bwy = f2[HW + r];

    Bilin bf = make_bilin(fwx, fwy, x, y);
    Bilin bb = make_bilin(bwx, bwy, x, y);

    // occ_fw = compute_occ(flow_fw, flow_bw)
    float bwwx = samp(f2, bf);
    float bwwy = samp(f2 + HW, bf);
    float dx0 = fwx + bwwx, dy0 = fwy + bwwy;
    float mag = dx0 * dx0 + dy0 * dy0;
    float fm  = fwx * fwx + fwy * fwy + bwwx * bwwx + bwwy * bwwy;
    float occf = (mag > fmaf(0.01f, fm, 0.5f)) ? 1.0f : 0.0f;
    out[3 + i] = occf;
    float mfw = 1.0f - occf;

    // occ_bw = compute_occ(flow_bw, flow_fw)
    float fwwx = samp(f1, bb);
    float fwwy = samp(f1 + HW, bb);
    float dx1 = bwx + fwwx, dy1 = bwy + fwwy;
    float mag1 = dx1 * dx1 + dy1 * dy1;
    float fm1  = bwx * bwx + bwy * bwy + fwwx * fwwx + fwwy * fwwy;
    float occb = (mag1 > fmaf(0.01f, fm1, 0.5f)) ? 1.0f : 0.0f;
    float mbw = 1.0f - occb;
    g_maskbw[i] = mbw;

    // image warps + photometric
    const float* i1 = img1 + (size_t)b * 3 * HW;
    const float* i2 = img2 + (size_t)b * 3 * HW;

    float w0 = samp(i2, bf), w1 = samp(i2 + HW, bf), w2 = samp(i2 + 2 * HW, bf);
    float a0 = i1[r], a1 = i1[HW + r], a2 = i1[2 * HW + r];
    float pfw = mfw * (__powf(fabsf(a0 - w0) + 0.01f, 0.4f)
                     + __powf(fabsf(a1 - w1) + 0.01f, 0.4f)
                     + __powf(fabsf(a2 - w2) + 0.01f, 0.4f));
    g_g2w[i] = (0.2989f * w0 + 0.587f * w1 + 0.114f * w2) * 255.0f;
    g_g1[i]  = (0.2989f * a0 + 0.587f * a1 + 0.114f * a2) * 255.0f;

    float v0 = samp(i1, bb), v1 = samp(i1 + HW, bb), v2 = samp(i1 + 2 * HW, bb);
    float c0 = i2[r], c1 = i2[HW + r], c2 = i2[2 * HW + r];
    float pbw = mbw * (__powf(fabsf(c0 - v0) + 0.01f, 0.4f)
                     + __powf(fabsf(c1 - v1) + 0.01f, 0.4f)
                     + __powf(fabsf(c2 - v2) + 0.01f, 0.4f));
    g_g1w[i] = (0.2989f * v0 + 0.587f * v1 + 0.114f * v2) * 255.0f;
    g_g2[i]  = (0.2989f * c0 + 0.587f * c1 + 0.114f * c2) * 255.0f;

    // block reduction: pfw, pbw, mfw, mbw
    float vals[4] = {pfw, pbw, mfw, mbw};
    __shared__ float red[8][4];
    int lane = threadIdx.x & 31, wid = threadIdx.x >> 5;
    #pragma unroll
    for (int k = 0; k < 4; k++) {
        float s = warp_reduce(vals[k]);
        if (lane == 0) red[wid][k] = s;
    }
    __syncthreads();
    if (threadIdx.x == 0) {
        float s0 = 0, s1 = 0, s2 = 0, s3 = 0;
        #pragma unroll
        for (int w = 0; w < 8; w++) { s0 += red[w][0]; s1 += red[w][1]; s2 += red[w][2]; s3 += red[w][3]; }
        atomicAdd(&g_acc[0], (double)s0);
        atomicAdd(&g_acc[1], (double)s1);
        atomicAdd(&g_acc[4], (double)s2);
        atomicAdd(&g_acc[5], (double)s3);
    }
}

// ---------------------------------------------------------------------------
// Census via symmetric edges, barrier-free sharing:
//   dist(p, +Delta) == dist(p+Delta, -Delta); center tap == 0.
// Each thread owns a column strip of CS=8 pixels. For each of the 24 forward
// offsets it computes the CS+dy edges originating in its own column (registers),
// takes the forward term from its own registers and the backward term from
// lane (tx - dx) via __shfl_sync. Boundary backward edges (origin column
// outside the warp) are covered by ONE extra predicated edge-block per offset,
// read from the smem x-halo and distributed with a second shfl + select.
// One __syncthreads per tile (after the value load); none in the hot loop.
// ---------------------------------------------------------------------------
constexpr int CTX = 32;                 // columns per tile (= warp width)
constexpr int CS  = 8;                  // rows per thread strip
constexpr int CWP = 8;                  // warps per block
constexpr int CTH = CS * CWP;           // tile height 64
constexpr int VH2 = CTH + 6, VW2 = CTX + 6;   // 70 x 38 value tile

__device__ __forceinline__ void edge2(float2 cf, float2 nf, float2 cb, float2 nb,
                                      float& ef, float& eb) {
    float d1 = nf.x - cf.x;
    float d2 = nf.y - cf.y;
    float t1 = d1 * rsqrtf(fmaf(d1, d1, 0.81f));
    float t2 = d2 * rsqrtf(fmaf(d2, d2, 0.81f));
    float df = t1 - t2;
    float q  = df * df;
    ef = __fdividef(q, 0.1f + q);
    float e1 = nb.x - cb.x;
    float e2 = nb.y - cb.y;
    float u1 = e1 * rsqrtf(fmaf(e1, e1, 0.81f));
    float u2 = e2 * rsqrtf(fmaf(e2, e2, 0.81f));
    float db = u1 - u2;
    float r  = db * db;
    eb = __fdividef(r, 0.1f + r);
}

__global__ void __launch_bounds__(256) k_census(const float* __restrict__ occ_fw) {
    __shared__ float2 vf[VH2][VW2];   // (g1,  g2w)  forward pair
    __shared__ float2 vb[VH2][VW2];   // (g2,  g1w)  backward pair
    __shared__ float2 red[CWP];

    int b   = blockIdx.z;
    int bx0 = blockIdx.x * CTX;
    int by0 = blockIdx.y * CTH;
    const float* p1  = g_g1  + (size_t)b * HW;
    const float* p2w = g_g2w + (size_t)b * HW;
    const float* p2  = g_g2  + (size_t)b * HW;
    const float* p1w = g_g1w + (size_t)b * HW;

    int tx  = threadIdx.x;            // lane = column
    int ty  = threadIdx.y;            // warp = row-strip
    int tid = ty * CTX + tx;
    int wy0 = ty * CS;                // strip base row within tile

    // Fill value tiles (zero padding outside image)
    for (int t = tid; t < VH2 * VW2; t += CTX * CWP) {
        int vy = t / VW2, vx = t - vy * VW2;
        int gy = by0 + vy - 3, gx = bx0 + vx - 3;
        float a = 0, bb2 = 0, c = 0, d = 0;
        if (gy >= 0 && gy < H && gx >= 0 && gx < W) {
            int gi = gy * W + gx;
            a = p1[gi]; bb2 = p2w[gi]; c = p2[gi]; d = p1w[gi];
        }
        vf[vy][vx] = make_float2(a, bb2);
        vb[vy][vx] = make_float2(c, d);
    }
    __syncthreads();

    // Forward offsets: (0,1..3) and (1..3, -3..3)
    constexpr int DYS[24] = {0,0,0, 1,1,1,1,1,1,1, 2,2,2,2,2,2,2, 3,3,3,3,3,3,3};
    constexpr int DXS[24] = {1,2,3, -3,-2,-1,0,1,2,3, -3,-2,-1,0,1,2,3, -3,-2,-1,0,1,2,3};

    float dsf[CS], dsb[CS];
    #pragma unroll
    for (int i = 0; i < CS; i++) { dsf[i] = 0.0f; dsb[i] = 0.0f; }

    #pragma unroll
    for (int k = 0; k < 24; k++) {
        const int dy  = DYS[k];
        const int dx  = DXS[k];
        const int adx = dx < 0 ? -dx : dx;
        const int NE  = CS + dy;      // edges per column: origin rows wy0-dy .. wy0+CS-1

        float ef[CS + 3], eb[CS + 3];
        #pragma unroll
        for (int j = 0; j < NE; j++) {
            int orow = wy0 - dy + j + 3;   // smem row of origin
            int ocol = tx + 3;
            float2 cf = vf[orow][ocol];
            float2 cb = vb[orow][ocol];
            float2 nf = vf[orow + dy][ocol + dx];
            float2 nb = vb[orow + dy][ocol + dx];
            edge2(cf, nf, cb, nb, ef[j], eb[j]);
        }

        float bef = 0.0f, beb = 0.0f;   // boundary edges, one block per offset
        if (adx) {
            int bcol = tx % adx;        // boundary column index 0..adx-1
            int brow = tx / adx;        // pixel row 0..CS-1
            if (tx < adx * CS) {
                int ocol = (dx > 0 ? bcol - dx : CTX + bcol) + 3;  // in x-halo
                int orow = wy0 + brow - dy + 3;
                float2 cf = vf[orow][ocol];
                float2 cb = vb[orow][ocol];
                float2 nf = vf[orow + dy][ocol + dx];
                float2 nb = vb[orow + dy][ocol + dx];
                edge2(cf, nf, cb, nb, bef, beb);
            }
        }

        #pragma unroll
        for (int i = 0; i < CS; i++) {
            float fwd_f = ef[i + dy];
            float fwd_b = eb[i + dy];
            float bwd_f, bwd_b;
            if (dx == 0) {
                bwd_f = ef[i];
                bwd_b = eb[i];
            } else {
                int src = tx - dx;
                float sf_ = __shfl_sync(0xFFFFFFFFu, ef[i], src & 31);
                float sb_ = __shfl_sync(0xFFFFFFFFu, eb[i], src & 31);
                int bidx = (dx > 0) ? tx : tx - (CTX + dx);  // this lane's boundary col idx
                int bsrc = (i * adx + bidx) & 31;            // lane holding that boundary edge
                float xf_ = __shfl_sync(0xFFFFFFFFu, bef, bsrc);
                float xb_ = __shfl_sync(0xFFFFFFFFu, beb, bsrc);
                bool out = (src < 0) | (src >= CTX);
                bwd_f = out ? xf_ : sf_;
                bwd_b = out ? xb_ : sb_;
            }
            dsf[i] += fwd_f + bwd_f;
            dsb[i] += fwd_b + bwd_b;
        }
    }

    // Per-pixel finalize over the strip + reduction
    float accf = 0.0f, accb = 0.0f;
    #pragma unroll
    for (int i = 0; i < CS; i++) {
        int gy = by0 + wy0 + i;
        int gx = bx0 + tx;
        int idx = b * HW + gy * W + gx;
        float maskf = 1.0f - occ_fw[idx];
        float maskb = g_maskbw[idx];
        accf += __powf(dsf[i] + 0.01f, 0.4f) * maskf;
        accb += __powf(dsb[i] + 0.01f, 0.4f) * maskb;
    }

    float sf = warp_reduce(accf);
    float sb = warp_reduce(accb);
    if (tx == 0) red[ty] = make_float2(sf, sb);
    __syncthreads();
    if (tid == 0) {
        float a = 0, c = 0;
        #pragma unroll
        for (int w = 0; w < CWP; w++) { a += red[w].x; c += red[w].y; }
        atomicAdd(&g_acc[2], (double)a);
        atomicAdd(&g_acc[3], (double)c);
    }
}

__global__ void k_final(float* __restrict__ out) {
    if (threadIdx.x == 0) {
        double dfw = g_acc[4] * 2.0 + 1e-6;
        double dbw = g_acc[5] * 2.0 + 1e-6;
        double photo  = g_acc[0] / dfw + g_acc[1] / dbw;
        double census = g_acc[2] / dfw + g_acc[3] / dbw;
        out[0] = (float)(photo + census);
        out[1] = (float)photo;
        out[2] = (float)census;
        // re-zero accumulators for the next call (graph replay safe:
        // globals are zero-initialized at load, and every call ends here)
        #pragma unroll
        for (int k = 0; k < 6; k++) g_acc[k] = 0.0;
    }
}

extern "C" void kernel_launch(void* const* d_in, const int* in_sizes, int n_in,
                              void* d_out, int out_size) {
    const float* img1 = (const float*)d_in[0];
    const float* img2 = (const float*)d_in[1];
    const float* ffw  = (const float*)d_in[2];
    const float* fbw  = (const float*)d_in[3];
    float* out = (float*)d_out;

    k_main<<<NPIX / 256, 256>>>(img1, img2, ffw, fbw, out);
    dim3 cg(W / CTX, H / CTH, B);
    dim3 cb(CTX, CWP, 1);
    k_census<<<cg, cb>>>(out + 3);
    k_final<<<1, 32>>>(out);
}

// round 7
// speedup vs baseline: 1.2558x; 1.2558x over previous
#include <cuda_runtime.h>
#include <math.h>

// Problem dims (fixed by setup_inputs)
constexpr int B = 8, H = 384, W = 768;
constexpr int HW = H * W;              // 294912
constexpr int NPIX = B * HW;           // 2359296

// Accumulators: 0 photo_fw, 1 photo_bw, 2 census_fw, 3 census_bw, 4 mask_fw_sum, 5 mask_bw_sum
// Zero-initialized at module load; k_final re-zeroes after reading each call.
__device__ double g_acc[6];

// Scratch gray maps (intensity*255) and backward mask
__device__ float g_g1[NPIX];    // gray(img1)*255
__device__ float g_g2[NPIX];    // gray(img2)*255
__device__ float g_g1w[NPIX];   // gray(warp(img1, flow_bw))*255
__device__ float g_g2w[NPIX];   // gray(warp(img2, flow_fw))*255
__device__ float g_maskbw[NPIX];

struct Bilin {
    int i00, i01, i10, i11;
    float w00, w01, w10, w11;
};

__device__ __forceinline__ Bilin make_bilin(float fx, float fy, int x, int y) {
    float gx = fminf(fmaxf(fx + (float)x, 0.0f), (float)(W - 1));
    float gy = fminf(fmaxf(fy + (float)y, 0.0f), (float)(H - 1));
    float x0 = floorf(gx), y0 = floorf(gy);
    float wx = gx - x0, wy = gy - y0;
    int x0i = (int)x0, y0i = (int)y0;
    int x1i = min(x0i + 1, W - 1);
    int y1i = min(y0i + 1, H - 1);
    Bilin b;
    b.i00 = y0i * W + x0i;
    b.i01 = y0i * W + x1i;
    b.i10 = y1i * W + x0i;
    b.i11 = y1i * W + x1i;
    float ix = 1.0f - wx, iy = 1.0f - wy;
    b.w00 = ix * iy; b.w01 = wx * iy; b.w10 = ix * wy; b.w11 = wx * wy;
    return b;
}

__device__ __forceinline__ float samp(const float* __restrict__ p, const Bilin& bl) {
    return bl.w00 * __ldg(p + bl.i00) + bl.w01 * __ldg(p + bl.i01)
         + bl.w10 * __ldg(p + bl.i10) + bl.w11 * __ldg(p + bl.i11);
}

__device__ __forceinline__ float warp_reduce(float v) {
    #pragma unroll
    for (int o = 16; o > 0; o >>= 1) v += __shfl_down_sync(0xFFFFFFFFu, v, o);
    return v;
}

// FMA-pipe reciprocal: bit-hack seed + 2 Newton iterations.
// For x in (0.1, 1.2] rel err ~1e-6. Keeps the MUFU pipe free.
__device__ __forceinline__ float rcp_fma(float x) {
    float r = __uint_as_float(0x7EF477D5u - __float_as_uint(x));
    r = r * (2.0f - x * r);
    r = r * (2.0f - x * r);
    return r;
}

// Per-pixel: occ fw/bw, photometric loss partials, gray maps
__global__ void __launch_bounds__(256) k_main(const float* __restrict__ img1,
                                              const float* __restrict__ img2,
                                              const float* __restrict__ ffw,
                                              const float* __restrict__ fbw,
                                              float* __restrict__ out) {
    int i = blockIdx.x * blockDim.x + threadIdx.x;   // grid sized exactly
    int b = i / HW;
    int r = i - b * HW;
    int y = r / W;
    int x = r - y * W;

    const float* f1 = ffw + (size_t)b * 2 * HW;
    const float* f2 = fbw + (size_t)b * 2 * HW;
    float fwx = f1[r],       fwy = f1[HW + r];
    float bwx = f2[r],       bwy = f2[HW + r];

    Bilin bf = make_bilin(fwx, fwy, x, y);
    Bilin bb = make_bilin(bwx, bwy, x, y);

    // occ_fw = compute_occ(flow_fw, flow_bw)
    float bwwx = samp(f2, bf);
    float bwwy = samp(f2 + HW, bf);
    float dx0 = fwx + bwwx, dy0 = fwy + bwwy;
    float mag = dx0 * dx0 + dy0 * dy0;
    float fm  = fwx * fwx + fwy * fwy + bwwx * bwwx + bwwy * bwwy;
    float occf = (mag > fmaf(0.01f, fm, 0.5f)) ? 1.0f : 0.0f;
    out[3 + i] = occf;
    float mfw = 1.0f - occf;

    // occ_bw = compute_occ(flow_bw, flow_fw)
    float fwwx = samp(f1, bb);
    float fwwy = samp(f1 + HW, bb);
    float dx1 = bwx + fwwx, dy1 = bwy + fwwy;
    float mag1 = dx1 * dx1 + dy1 * dy1;
    float fm1  = bwx * bwx + bwy * bwy + fwwx * fwwx + fwwy * fwwy;
    float occb = (mag1 > fmaf(0.01f, fm1, 0.5f)) ? 1.0f : 0.0f;
    float mbw = 1.0f - occb;
    g_maskbw[i] = mbw;

    // image warps + photometric
    const float* i1 = img1 + (size_t)b * 3 * HW;
    const float* i2 = img2 + (size_t)b * 3 * HW;

    float w0 = samp(i2, bf), w1 = samp(i2 + HW, bf), w2 = samp(i2 + 2 * HW, bf);
    float a0 = i1[r], a1 = i1[HW + r], a2 = i1[2 * HW + r];
    float pfw = mfw * (__powf(fabsf(a0 - w0) + 0.01f, 0.4f)
                     + __powf(fabsf(a1 - w1) + 0.01f, 0.4f)
                     + __powf(fabsf(a2 - w2) + 0.01f, 0.4f));
    g_g2w[i] = (0.2989f * w0 + 0.587f * w1 + 0.114f * w2) * 255.0f;
    g_g1[i]  = (0.2989f * a0 + 0.587f * a1 + 0.114f * a2) * 255.0f;

    float v0 = samp(i1, bb), v1 = samp(i1 + HW, bb), v2 = samp(i1 + 2 * HW, bb);
    float c0 = i2[r], c1 = i2[HW + r], c2 = i2[2 * HW + r];
    float pbw = mbw * (__powf(fabsf(c0 - v0) + 0.01f, 0.4f)
                     + __powf(fabsf(c1 - v1) + 0.01f, 0.4f)
                     + __powf(fabsf(c2 - v2) + 0.01f, 0.4f));
    g_g1w[i] = (0.2989f * v0 + 0.587f * v1 + 0.114f * v2) * 255.0f;
    g_g2[i]  = (0.2989f * c0 + 0.587f * c1 + 0.114f * c2) * 255.0f;

    // block reduction: pfw, pbw, mfw, mbw
    float vals[4] = {pfw, pbw, mfw, mbw};
    __shared__ float red[8][4];
    int lane = threadIdx.x & 31, wid = threadIdx.x >> 5;
    #pragma unroll
    for (int k = 0; k < 4; k++) {
        float s = warp_reduce(vals[k]);
        if (lane == 0) red[wid][k] = s;
    }
    __syncthreads();
    if (threadIdx.x == 0) {
        float s0 = 0, s1 = 0, s2 = 0, s3 = 0;
        #pragma unroll
        for (int w = 0; w < 8; w++) { s0 += red[w][0]; s1 += red[w][1]; s2 += red[w][2]; s3 += red[w][3]; }
        atomicAdd(&g_acc[0], (double)s0);
        atomicAdd(&g_acc[1], (double)s1);
        atomicAdd(&g_acc[4], (double)s2);
        atomicAdd(&g_acc[5], (double)s3);
    }
}

// ---------------------------------------------------------------------------
// Census: direct 48-tap form (round-1 structure), with
//  - center tap skipped (identically zero)
//  - maps packed as float2 pairs (halves LDS instruction count)
//  - 1/3 of the per-tap divides moved to the FMA pipe (Newton rcp) so the
//    MUFU and FMA pipes are load-balanced (~2048 cyc each per warp)
// ---------------------------------------------------------------------------
constexpr int TX = 32, TY = 8;
constexpr int SW = TX + 6, SH = TY + 6;   // 38 x 14 value tile

__global__ void __launch_bounds__(256) k_census(const float* __restrict__ occ_fw) {
    __shared__ float2 vf[SH][SW];   // (g1, g2w)  forward pair
    __shared__ float2 vb[SH][SW];   // (g2, g1w)  backward pair
    __shared__ float2 red[8];

    int b   = blockIdx.z;
    int bx0 = blockIdx.x * TX;
    int by0 = blockIdx.y * TY;
    const float* p1  = g_g1  + (size_t)b * HW;
    const float* p2w = g_g2w + (size_t)b * HW;
    const float* p2  = g_g2  + (size_t)b * HW;
    const float* p1w = g_g1w + (size_t)b * HW;

    int tid = threadIdx.y * TX + threadIdx.x;
    for (int t = tid; t < SH * SW; t += TX * TY) {
        int ly = t / SW, lx = t - ly * SW;
        int gy = by0 + ly - 3, gx = bx0 + lx - 3;
        float a = 0, bb = 0, c = 0, d = 0;
        if (gy >= 0 && gy < H && gx >= 0 && gx < W) {
            int gi = gy * W + gx;
            a = p1[gi]; bb = p2w[gi]; c = p2[gi]; d = p1w[gi];
        }
        vf[ly][lx] = make_float2(a, bb);
        vb[ly][lx] = make_float2(c, d);
    }
    __syncthreads();

    int lx = threadIdx.x, ly = threadIdx.y;
    float2 cf = vf[ly + 3][lx + 3];
    float2 cb = vb[ly + 3][lx + 3];

    float dsf = 0.0f, dsb = 0.0f;
    #pragma unroll
    for (int dy = 0; dy < 7; dy++) {
        #pragma unroll
        for (int dx = 0; dx < 7; dx++) {
            if (dy == 3 && dx == 3) continue;         // center tap == 0
            const bool NEWTON = ((dy * 7 + dx) % 3) == 0;   // 16 of 48 taps

            float2 nf = vf[ly + dy][lx + dx];
            float2 nb = vb[ly + dy][lx + dx];

            // pair fw: (img1, img2_warped)
            float d1 = nf.x - cf.x;
            float t1 = d1 * rsqrtf(fmaf(d1, d1, 0.81f));
            float d2 = nf.y - cf.y;
            float t2 = d2 * rsqrtf(fmaf(d2, d2, 0.81f));
            float df = t1 - t2;
            float dd = df * df;
            if (NEWTON) dsf += dd * rcp_fma(0.1f + dd);
            else        dsf += __fdividef(dd, 0.1f + dd);

            // pair bw: (img2, img1_warped)
            float e1 = nb.x - cb.x;
            float u1 = e1 * rsqrtf(fmaf(e1, e1, 0.81f));
            float e2 = nb.y - cb.y;
            float u2 = e2 * rsqrtf(fmaf(e2, e2, 0.81f));
            float db = u1 - u2;
            float ee = db * db;
            if (NEWTON) dsb += ee * rcp_fma(0.1f + ee);
            else        dsb += __fdividef(ee, 0.1f + ee);
        }
    }

    int gy = by0 + ly, gx = bx0 + lx;
    int i = b * HW + gy * W + gx;
    float maskf = 1.0f - occ_fw[i];
    float maskb = g_maskbw[i];
    float cfv = __powf(dsf + 0.01f, 0.4f) * maskf;
    float cbv = __powf(dsb + 0.01f, 0.4f) * maskb;

    int lane = tid & 31, wid = tid >> 5;
    float sf = warp_reduce(cfv);
    float sb = warp_reduce(cbv);
    if (lane == 0) red[wid] = make_float2(sf, sb);
    __syncthreads();
    if (tid == 0) {
        float a = 0, c = 0;
        #pragma unroll
        for (int w = 0; w < 8; w++) { a += red[w].x; c += red[w].y; }
        atomicAdd(&g_acc[2], (double)a);
        atomicAdd(&g_acc[3], (double)c);
    }
}

__global__ void k_final(float* __restrict__ out) {
    if (threadIdx.x == 0) {
        double dfw = g_acc[4] * 2.0 + 1e-6;
        double dbw = g_acc[5] * 2.0 + 1e-6;
        double photo  = g_acc[0] / dfw + g_acc[1] / dbw;
        double census = g_acc[2] / dfw + g_acc[3] / dbw;
        out[0] = (float)(photo + census);
        out[1] = (float)photo;
        out[2] = (float)census;
        // re-zero accumulators for the next call (graph replay safe:
        // globals are zero-initialized at load, and every call ends here)
        #pragma unroll
        for (int k = 0; k < 6; k++) g_acc[k] = 0.0;
    }
}

extern "C" void kernel_launch(void* const* d_in, const int* in_sizes, int n_in,
                              void* d_out, int out_size) {
    const float* img1 = (const float*)d_in[0];
    const float* img2 = (const float*)d_in[1];
    const float* ffw  = (const float*)d_in[2];
    const float* fbw  = (const float*)d_in[3];
    float* out = (float*)d_out;

    k_main<<<NPIX / 256, 256>>>(img1, img2, ffw, fbw, out);
    dim3 cg(W / TX, H / TY, B);
    dim3 cb(TX, TY, 1);
    k_census<<<cg, cb>>>(out + 3);
    k_final<<<1, 32>>>(out);
}